// round 4
// baseline (speedup 1.0000x reference)
#include <cuda_runtime.h>
#include <mma.h>
#include <math.h>
#include <stdint.h>

using namespace nvcuda;

// ---------------- problem constants ----------------
#define NES   4096          // E*S
#define VOBS  128
#define KOBS  32
#define H     256
#define LSEQ  32
#define VCOMM 32
#define NL    131072        // NES*LSEQ

// ---------------- device scratch (no allocation allowed) ----------------
__device__ __align__(16) float g_M[VOBS * KOBS * H];
__device__ __align__(16) float g_U[32768];
__device__ int   g_idx[NES * KOBS];
__device__ int   g_tok[NES * LSEQ];
__device__ __align__(16) float g_conv[NL * H];                 // [m=n*32+l][c]
__device__ __align__(16) float g_bnPart[512 * 512];
__device__ float g_bnS[H], g_bnT[H];
__device__ __align__(16) float g_xproj[(size_t)NL * 768];      // [m][g*256+j]
__device__ __align__(16) float g_G[(size_t)NES * 768];         // gate pre-activations
__device__ __align__(16) float g_h[2][NES * H];                // GRU state ping-pong

// ---------------- K: init (zero h0) ----------------
__global__ void k_init() {
    int t = blockIdx.x * blockDim.x + threadIdx.x;
    for (int i = t; i < NES * H; i += 256 * 256) g_h[0][i] = 0.f;
}

// ---------------- K: extract obs indices + comm argmax ----------------
__global__ void k_extract(const float* __restrict__ obs, const float* __restrict__ comm) {
    int m = blockIdx.x;
    int lane = threadIdx.x & 31;
    if (threadIdx.x < 32) {
        const float* o = obs + m * VOBS;
        int base = 0;
        #pragma unroll
        for (int c = 0; c < 4; c++) {
            float v = o[c * 32 + lane];
            unsigned mask = __ballot_sync(0xffffffffu, v > 0.5f);
            if (v > 0.5f) {
                int pos = base + __popc(mask & ((1u << lane) - 1u));
                g_idx[m * KOBS + pos] = c * 32 + lane;
            }
            base += __popc(mask);
        }
    } else {
        int l = lane;
        const float* cm = comm + (m * LSEQ + l) * VCOMM;
        float best = cm[0]; int bi = 0;
        #pragma unroll
        for (int v = 1; v < VCOMM; v++) { float x = cm[v]; if (x > best) { best = x; bi = v; } }
        g_tok[m * LSEQ + l] = bi;
    }
}

// ---------------- K: obs table M[i][k][j] ----------------
__global__ void k_obsM(const float* __restrict__ emb, const float* __restrict__ W,
                       const float* __restrict__ a_emb_p) {
    __shared__ float Ps[16][256];
    int k = blockIdx.x, i0 = blockIdx.y * 16;
    float a = a_emb_p[0];
    int tid = threadIdx.x;
    for (int r = tid; r < 16 * 256; r += 256) {
        int i = r >> 8, h = r & 255;
        float v = emb[(i0 + i) * H + h];
        Ps[i][h] = v >= 0.f ? v : a * v;
    }
    __syncthreads();
    float acc[16];
    #pragma unroll
    for (int i = 0; i < 16; i++) acc[i] = 0.f;
    int j = tid;
    const float* Wk = W + (k * H) * H + j;
    for (int h = 0; h < H; h++) {
        float w = Wk[h * H];
        #pragma unroll
        for (int i = 0; i < 16; i++) acc[i] = fmaf(Ps[i][h], w, acc[i]);
    }
    #pragma unroll
    for (int i = 0; i < 16; i++)
        g_M[((i0 + i) * KOBS + k) * H + j] = acc[i];
}

// ---------------- K: conv token table U ----------------
__global__ void k_commU(const float* __restrict__ ce, const float* __restrict__ a_emb_p,
                        const float* __restrict__ w1, const float* __restrict__ w3,
                        const float* __restrict__ w5, const float* __restrict__ w7) {
    extern __shared__ float smc[];
    float* sE = smc;
    float* sW = smc + 8192;
    int g = blockIdx.x, d = blockIdx.y;
    int ks = 2 * g + 1;
    if (d >= ks) return;
    const float* w = (g == 0) ? w1 : (g == 1) ? w3 : (g == 2) ? w5 : w7;
    int tid = threadIdx.x;
    float a = a_emb_p[0];
    for (int v = tid; v < 8192; v += 256) {
        float e = ce[v];
        sE[v] = e >= 0.f ? e : a * e;
    }
    for (int v = tid; v < 16384; v += 256) {
        int cg = v >> 8, h = v & 255;
        sW[cg * 257 + h] = w[(cg * 256 + h) * ks + d];
    }
    __syncthreads();
    int cg = tid & 63, t0 = (tid >> 6) * 8;
    float acc[8];
    #pragma unroll
    for (int t = 0; t < 8; t++) acc[t] = 0.f;
    for (int h = 0; h < 256; h++) {
        float wv = sW[cg * 257 + h];
        #pragma unroll
        for (int t = 0; t < 8; t++) acc[t] = fmaf(sE[(t0 + t) * 256 + h], wv, acc[t]);
    }
    int segoff = (g == 0) ? 0 : (g == 1) ? 2048 : (g == 2) ? 8192 : 18432;
    #pragma unroll
    for (int t = 0; t < 8; t++)
        g_U[segoff + (d * 32 + t0 + t) * 64 + cg] = acc[t];
}

// ---------------- K: conv via table lookups + BN partial stats ----------------
__global__ void k_conv() {
    extern __shared__ float sm[];
    float* sU   = sm;
    float* sRed = sm + 32768;
    __shared__ int sTok[256];
    int tx = threadIdx.x, ty = threadIdx.y;
    int tid = ty * 64 + tx;
    int n0 = blockIdx.x * 8;
    const float4* gU4 = (const float4*)g_U;
    float4* sU4 = (float4*)sU;
    for (int v = tid; v < 8192; v += 256) sU4[v] = gU4[v];
    if (tid < 256) sTok[tid] = g_tok[n0 * LSEQ + tid];
    __syncthreads();

    int g = tx >> 4, ks = 2 * g + 1, pad = g;
    int seg4 = (g == 0) ? 0 : (g == 1) ? 512 : (g == 2) ? 2048 : 4608;
    int cm = tx & 15;
    const float4* U4 = (const float4*)sU;
    float lsum[4] = {0, 0, 0, 0}, lsq[4] = {0, 0, 0, 0};

    for (int half = 0; half < 2; half++) {
        int nl = ty + 4 * half;
        int n = n0 + nl;
        const int* tk = sTok + nl * LSEQ;
        for (int l = 0; l < LSEQ; l++) {
            float4 acc = make_float4(0.f, 0.f, 0.f, 0.f);
            #pragma unroll
            for (int d = 0; d < 7; d++) {
                int lp = l + d - pad;
                if (d < ks && lp >= 0 && lp < LSEQ) {
                    float4 u = U4[seg4 + (d * 32 + tk[lp]) * 16 + cm];
                    acc.x += u.x; acc.y += u.y; acc.z += u.z; acc.w += u.w;
                }
            }
            ((float4*)g_conv)[(n * LSEQ + l) * 64 + tx] = acc;
            lsum[0] += acc.x; lsum[1] += acc.y; lsum[2] += acc.z; lsum[3] += acc.w;
            lsq[0] += acc.x * acc.x; lsq[1] += acc.y * acc.y;
            lsq[2] += acc.z * acc.z; lsq[3] += acc.w * acc.w;
        }
    }
    #pragma unroll
    for (int e = 0; e < 4; e++) {
        sRed[ty * 512 + 4 * tx + e]       = lsum[e];
        sRed[ty * 512 + 256 + 4 * tx + e] = lsq[e];
    }
    __syncthreads();
    if (tid < 256) {
        float s = sRed[tid] + sRed[512 + tid] + sRed[1024 + tid] + sRed[1536 + tid];
        float q = sRed[256 + tid] + sRed[768 + tid] + sRed[1280 + tid] + sRed[1792 + tid];
        g_bnPart[blockIdx.x * 512 + tid]       = s;
        g_bnPart[blockIdx.x * 512 + 256 + tid] = q;
    }
}

// ---------------- K: finalize BN ----------------
__global__ void k_bnfin(const float* __restrict__ bn_g, const float* __restrict__ bn_b) {
    int c = threadIdx.x;
    double s = 0.0, q = 0.0;
    for (int b = 0; b < 512; b++) {
        s += (double)g_bnPart[b * 512 + c];
        q += (double)g_bnPart[b * 512 + 256 + c];
    }
    double mean = s / (double)NL;
    double var  = q / (double)NL - mean * mean;
    float sc = (float)((double)bn_g[c] / sqrt(var + 1e-5));
    g_bnS[c] = sc;
    g_bnT[c] = bn_b[c] - sc * (float)mean;
}

// ---------------- K: wmma tf32 GEMM  C[M x 768] = A[M x 256] @ W[g][256][256] ----------------
// MODE 0: A = prelu(BN(g_conv)) fused on load, C = g_xproj
// MODE 1: A = g_h[hin],                        C = g_G
// CTA tile 128x128, 8 warps, warp tile 32x64, K-chunk 32.
template<int MODE>
__global__ void __launch_bounds__(256) k_gemm(int hin, const float* __restrict__ W,
                                              const float* __restrict__ prelu_a) {
    __shared__ float As[128][36];
    __shared__ float Bs[32][132];
    int tid = threadIdx.x;
    int wid = tid >> 5;
    int wr = wid & 3, wc = wid >> 2;
    int m0 = blockIdx.x * 128;
    int nc0 = blockIdx.y * 128;
    const float* A = (MODE == 0) ? g_conv : g_h[hin];
    float* C = (MODE == 0) ? g_xproj : g_G;
    const float* Bp = W + (nc0 >> 8) * 65536 + (nc0 & 255);
    float ca = (MODE == 0) ? prelu_a[0] : 0.f;

    wmma::fragment<wmma::accumulator, 16, 16, 8, float> acc[2][4];
    #pragma unroll
    for (int i = 0; i < 2; i++)
        #pragma unroll
        for (int j = 0; j < 4; j++) wmma::fill_fragment(acc[i][j], 0.f);

    int arow = tid >> 1, acs = (tid & 1) * 16;
    int brow = tid >> 3, bcs = (tid & 7) * 16;

    for (int k0 = 0; k0 < 256; k0 += 32) {
        const float* Ag = A + (size_t)(m0 + arow) * 256 + k0 + acs;
        #pragma unroll
        for (int q = 0; q < 4; q++) {
            float4 v = *(const float4*)(Ag + 4 * q);
            if (MODE == 0) {
                int c = k0 + acs + 4 * q;
                float x;
                x = fmaf(g_bnS[c + 0], v.x, g_bnT[c + 0]); v.x = x >= 0.f ? x : ca * x;
                x = fmaf(g_bnS[c + 1], v.y, g_bnT[c + 1]); v.y = x >= 0.f ? x : ca * x;
                x = fmaf(g_bnS[c + 2], v.z, g_bnT[c + 2]); v.z = x >= 0.f ? x : ca * x;
                x = fmaf(g_bnS[c + 3], v.w, g_bnT[c + 3]); v.w = x >= 0.f ? x : ca * x;
            }
            As[arow][acs + 4 * q + 0] = wmma::__float_to_tf32(v.x);
            As[arow][acs + 4 * q + 1] = wmma::__float_to_tf32(v.y);
            As[arow][acs + 4 * q + 2] = wmma::__float_to_tf32(v.z);
            As[arow][acs + 4 * q + 3] = wmma::__float_to_tf32(v.w);
        }
        const float* Bg = Bp + (size_t)(k0 + brow) * 256 + bcs;
        #pragma unroll
        for (int q = 0; q < 4; q++) {
            float4 v = *(const float4*)(Bg + 4 * q);
            Bs[brow][bcs + 4 * q + 0] = wmma::__float_to_tf32(v.x);
            Bs[brow][bcs + 4 * q + 1] = wmma::__float_to_tf32(v.y);
            Bs[brow][bcs + 4 * q + 2] = wmma::__float_to_tf32(v.z);
            Bs[brow][bcs + 4 * q + 3] = wmma::__float_to_tf32(v.w);
        }
        __syncthreads();
        #pragma unroll
        for (int kk = 0; kk < 4; kk++) {
            wmma::fragment<wmma::matrix_a, 16, 16, 8, wmma::precision::tf32, wmma::row_major> a0, a1;
            wmma::load_matrix_sync(a0, &As[wr * 32][kk * 8], 36);
            wmma::load_matrix_sync(a1, &As[wr * 32 + 16][kk * 8], 36);
            #pragma unroll
            for (int j = 0; j < 4; j++) {
                wmma::fragment<wmma::matrix_b, 16, 16, 8, wmma::precision::tf32, wmma::row_major> b;
                wmma::load_matrix_sync(b, &Bs[kk * 8][wc * 64 + j * 16], 132);
                wmma::mma_sync(acc[0][j], a0, b, acc[0][j]);
                wmma::mma_sync(acc[1][j], a1, b, acc[1][j]);
            }
        }
        __syncthreads();
    }
    #pragma unroll
    for (int i = 0; i < 2; i++)
        #pragma unroll
        for (int j = 0; j < 4; j++) {
            float* dst = C + (size_t)(m0 + wr * 32 + i * 16) * 768 + nc0 + wc * 64 + j * 16;
            wmma::store_matrix_sync(dst, acc[i][j], 768, wmma::mem_row_major);
        }
}

// ---------------- K: GRU gate elementwise (per step) ----------------
__global__ void k_gate(int l, int hin, const float* __restrict__ bh,
                       const float* __restrict__ bx) {
    int i = blockIdx.x * 256 + threadIdx.x;
    int n = i >> 8, j = i & 255;
    float h = g_h[hin][i];
    const float* G = g_G + (size_t)n * 768 + j;
    float gr = G[0]   + __ldg(&bh[j]);
    float gz = G[256] + __ldg(&bh[256 + j]);
    float gn = G[512] + __ldg(&bh[512 + j]);
    size_t m = (size_t)n * 32 + l;
    const float* xp = g_xproj + m * 768 + j;
    float xr = xp[0]   + __ldg(&bx[j]);
    float xz = xp[256] + __ldg(&bx[256 + j]);
    float xn = xp[512] + __ldg(&bx[512 + j]);
    float r = __fdividef(1.f, 1.f + __expf(-(xr + gr)));
    float z = __fdividef(1.f, 1.f + __expf(-(xz + gz)));
    float arg = xn + r * gn;
    float e2 = __expf(2.f * arg);
    float th = 1.f - __fdividef(2.f, e2 + 1.f);
    g_h[hin ^ 1][i] = th + z * (h - th);
}

// ---------------- K: final linear on c-path ----------------
__global__ void k_final(const float* __restrict__ Wl, const float* __restrict__ bl,
                        const float* __restrict__ a1p, const float* __restrict__ a2p,
                        float* __restrict__ out) {
    __shared__ float As[16 * 68];
    __shared__ float Bs[16 * 64];
    int m0 = blockIdx.x * 64;
    int j0 = blockIdx.y * 64;
    float a1 = a1p[0], a2 = a2p[0];
    const float* A = g_h[0];
    int tid = threadIdx.x;
    int tx = tid & 15, ty = tid >> 4;
    float acc[4][4];
    #pragma unroll
    for (int i = 0; i < 4; i++)
        #pragma unroll
        for (int j = 0; j < 4; j++) acc[i][j] = 0.f;

    for (int k0 = 0; k0 < H; k0 += 16) {
        int row = tid >> 2, segc = tid & 3;
        float4 a4 = *(const float4*)&A[(m0 + row) * H + k0 + 4 * segc];
        float av[4] = {a4.x, a4.y, a4.z, a4.w};
        #pragma unroll
        for (int e = 0; e < 4; e++) {
            float x = av[e];
            As[(4 * segc + e) * 68 + row] = x >= 0.f ? x : a1 * x;
        }
        int rowk = tid >> 4, jc = tid & 15;
        float4 b4 = *(const float4*)&Wl[(k0 + rowk) * H + j0 + 4 * jc];
        *(float4*)&Bs[rowk * 64 + 4 * jc] = b4;
        __syncthreads();
        #pragma unroll
        for (int k = 0; k < 16; k++) {
            float a[4], b[4];
            *(float4*)a = *(const float4*)&As[k * 68 + ty * 4];
            *(float4*)b = *(const float4*)&Bs[k * 64 + tx * 4];
            #pragma unroll
            for (int i = 0; i < 4; i++)
                #pragma unroll
                for (int j = 0; j < 4; j++)
                    acc[i][j] = fmaf(a[i], b[j], acc[i][j]);
        }
        __syncthreads();
    }
    #pragma unroll
    for (int i = 0; i < 4; i++) {
        int m = m0 + ty * 4 + i;
        #pragma unroll
        for (int j = 0; j < 4; j++) {
            int jj = j0 + tx * 4 + j;
            float v = acc[i][j] + bl[jj];
            v = v >= 0.f ? v : a2 * v;
            out[m * 512 + 256 + jj] = v;
        }
    }
}

// ---------------- K: obs output ----------------
__global__ void k_obsout(const float* __restrict__ obs_b, const float* __restrict__ obs_a_p,
                         float* __restrict__ out) {
    int m = blockIdx.x;
    int j = threadIdx.x;
    __shared__ int si[KOBS];
    if (j < KOBS) si[j] = g_idx[m * KOBS + j];
    __syncthreads();
    float acc = obs_b[j];
    #pragma unroll
    for (int k = 0; k < KOBS; k++)
        acc += g_M[(si[k] * KOBS + k) * H + j];
    float a = obs_a_p[0];
    out[m * 512 + j] = acc >= 0.f ? acc : a * acc;
}

// ---------------- host launch ----------------
extern "C" void kernel_launch(void* const* d_in, const int* in_sizes, int n_in,
                              void* d_out, int out_size) {
    const float* obs        = (const float*)d_in[0];
    const float* comm       = (const float*)d_in[1];
    const float* obs_emb    = (const float*)d_in[2];
    const float* obs_a_emb  = (const float*)d_in[3];
    const float* obs_W      = (const float*)d_in[4];
    const float* obs_b      = (const float*)d_in[5];
    const float* obs_a      = (const float*)d_in[6];
    const float* comm_emb   = (const float*)d_in[7];
    const float* comm_a_emb = (const float*)d_in[8];
    const float* cw1        = (const float*)d_in[9];
    const float* cw3        = (const float*)d_in[11];
    const float* cw5        = (const float*)d_in[13];
    const float* cw7        = (const float*)d_in[15];
    const float* bn_g       = (const float*)d_in[17];
    const float* bn_b       = (const float*)d_in[18];
    const float* cnn_a      = (const float*)d_in[19];
    const float* Wx         = (const float*)d_in[20];
    const float* bx         = (const float*)d_in[21];
    const float* Wh         = (const float*)d_in[22];
    const float* bh         = (const float*)d_in[23];
    const float* lin_a1     = (const float*)d_in[24];
    const float* lin_W      = (const float*)d_in[25];
    const float* lin_b      = (const float*)d_in[26];
    const float* lin_a2     = (const float*)d_in[27];
    float* out = (float*)d_out;

    cudaFuncSetAttribute(k_conv,  cudaFuncAttributeMaxDynamicSharedMemorySize, 139264);
    cudaFuncSetAttribute(k_commU, cudaFuncAttributeMaxDynamicSharedMemorySize, 98560);

    k_init<<<256, 256>>>();                                           // 0
    k_extract<<<NES, 64>>>(obs, comm);                                // 1
    k_commU<<<dim3(4, 7), 256, 98560>>>(comm_emb, comm_a_emb, cw1, cw3, cw5, cw7); // 2
    k_gemm<1><<<dim3(32, 6), 256>>>(0, Wh, nullptr);                  // 3  step0 G (h0 = 0)
    k_conv<<<512, dim3(64, 4), 139264>>>();                           // 4
    k_bnfin<<<1, 256>>>(bn_g, bn_b);                                  // 5
    k_gemm<0><<<dim3(1024, 6), 256>>>(0, Wx, cnn_a);                  // 6  xproj
    k_obsM<<<dim3(32, 8), 256>>>(obs_emb, obs_W, obs_a_emb);          // 7
    k_gate<<<NES, 256>>>(0, 0, bh, bx);                               // 8

    int hin = 1;
    for (int l = 1; l < LSEQ; l++) {
        k_gemm<1><<<dim3(32, 6), 256>>>(hin, Wh, nullptr);
        k_gate<<<NES, 256>>>(l, hin, bh, bx);
        hin ^= 1;
    }
    // after 32 gate steps, final state is in g_h[0]
    k_final<<<dim3(64, 4), 256>>>(lin_W, lin_b, lin_a1, lin_a2, out);
    k_obsout<<<NES, 256>>>(obs_b, obs_a, out);
}

// round 5
// speedup vs baseline: 3.5268x; 3.5268x over previous
#include <cuda_runtime.h>
#include <cuda_fp16.h>
#include <math.h>
#include <stdint.h>

// ---------------- problem constants ----------------
#define NES   4096          // E*S
#define VOBS  128
#define KOBS  32
#define H     256
#define LSEQ  32
#define VCOMM 32
#define NL    131072        // NES*LSEQ

// ---------------- device scratch (no allocation allowed) ----------------
__device__ __align__(16) float  g_M[VOBS * KOBS * H];
__device__ __align__(16) float  g_U[32768];
__device__ int    g_idx[NES * KOBS];
__device__ int    g_tok[NES * LSEQ];
__device__ __align__(16) __half g_conv16[NL * H];               // [m=n*32+l][c] half
__device__ __align__(16) float  g_bnPart[512 * 512];
__device__ float  g_bnS[H], g_bnT[H];
__device__ __align__(16) float  g_xproj[(size_t)NL * 768];      // [m][g*256+j]
__device__ __align__(16) float  g_G[(size_t)NES * 768];
__device__ __align__(16) float  g_h[2][NES * H];
__device__ __align__(16) __half g_h16[NES * H];                 // latest h, half
__device__ __align__(16) __half g_W16[2][3 * 65536];            // [0]=Wx^T,[1]=Wh^T : [g][n][k] half

// ---------------- K: init ----------------
__global__ void k_init() {
    int t = blockIdx.x * blockDim.x + threadIdx.x;
    for (int i = t; i < NES * H; i += 256 * 256) {
        g_h[0][i] = 0.f;
        g_h16[i] = __float2half(0.f);
    }
}

// ---------------- K: transpose+convert Wx, Wh -> g_W16[mat][g][n][k] half ----------------
__global__ void k_prep(const float* __restrict__ Wx, const float* __restrict__ Wh) {
    __shared__ float t[32][33];
    int mat = blockIdx.z / 3, g = blockIdx.z % 3;
    const float* src = (mat ? Wh : Wx) + g * 65536;   // [k][n]
    __half* dst = g_W16[mat] + g * 65536;             // [n][k]
    int x0 = blockIdx.x * 32, y0 = blockIdx.y * 32;
    int tx = threadIdx.x, ty = threadIdx.y;
    #pragma unroll
    for (int r = 0; r < 32; r += 8)
        t[ty + r][tx] = src[(y0 + ty + r) * 256 + x0 + tx];
    __syncthreads();
    #pragma unroll
    for (int r = 0; r < 32; r += 8)
        dst[(x0 + ty + r) * 256 + y0 + tx] = __float2half(t[tx][ty + r]);
}

// ---------------- K: extract obs indices + comm argmax ----------------
__global__ void k_extract(const float* __restrict__ obs, const float* __restrict__ comm) {
    int m = blockIdx.x;
    int lane = threadIdx.x & 31;
    if (threadIdx.x < 32) {
        const float* o = obs + m * VOBS;
        int base = 0;
        #pragma unroll
        for (int c = 0; c < 4; c++) {
            float v = o[c * 32 + lane];
            unsigned mask = __ballot_sync(0xffffffffu, v > 0.5f);
            if (v > 0.5f) {
                int pos = base + __popc(mask & ((1u << lane) - 1u));
                g_idx[m * KOBS + pos] = c * 32 + lane;
            }
            base += __popc(mask);
        }
    } else {
        int l = lane;
        const float* cm = comm + (m * LSEQ + l) * VCOMM;
        float best = cm[0]; int bi = 0;
        #pragma unroll
        for (int v = 1; v < VCOMM; v++) { float x = cm[v]; if (x > best) { best = x; bi = v; } }
        g_tok[m * LSEQ + l] = bi;
    }
}

// ---------------- K: obs table M ----------------
__global__ void k_obsM(const float* __restrict__ emb, const float* __restrict__ W,
                       const float* __restrict__ a_emb_p) {
    __shared__ float Ps[16][256];
    int k = blockIdx.x, i0 = blockIdx.y * 16;
    float a = a_emb_p[0];
    int tid = threadIdx.x;
    for (int r = tid; r < 16 * 256; r += 256) {
        int i = r >> 8, h = r & 255;
        float v = emb[(i0 + i) * H + h];
        Ps[i][h] = v >= 0.f ? v : a * v;
    }
    __syncthreads();
    float acc[16];
    #pragma unroll
    for (int i = 0; i < 16; i++) acc[i] = 0.f;
    int j = tid;
    const float* Wk = W + (k * H) * H + j;
    for (int h = 0; h < H; h++) {
        float w = Wk[h * H];
        #pragma unroll
        for (int i = 0; i < 16; i++) acc[i] = fmaf(Ps[i][h], w, acc[i]);
    }
    #pragma unroll
    for (int i = 0; i < 16; i++)
        g_M[((i0 + i) * KOBS + k) * H + j] = acc[i];
}

// ---------------- K: conv token table U ----------------
__global__ void k_commU(const float* __restrict__ ce, const float* __restrict__ a_emb_p,
                        const float* __restrict__ w1, const float* __restrict__ w3,
                        const float* __restrict__ w5, const float* __restrict__ w7) {
    extern __shared__ float smc[];
    float* sE = smc;
    float* sW = smc + 8192;
    int g = blockIdx.x, d = blockIdx.y;
    int ks = 2 * g + 1;
    if (d >= ks) return;
    const float* w = (g == 0) ? w1 : (g == 1) ? w3 : (g == 2) ? w5 : w7;
    int tid = threadIdx.x;
    float a = a_emb_p[0];
    for (int v = tid; v < 8192; v += 256) {
        float e = ce[v];
        sE[v] = e >= 0.f ? e : a * e;
    }
    for (int v = tid; v < 16384; v += 256) {
        int cg = v >> 8, h = v & 255;
        sW[cg * 257 + h] = w[(cg * 256 + h) * ks + d];
    }
    __syncthreads();
    int cg = tid & 63, t0 = (tid >> 6) * 8;
    float acc[8];
    #pragma unroll
    for (int t = 0; t < 8; t++) acc[t] = 0.f;
    for (int h = 0; h < 256; h++) {
        float wv = sW[cg * 257 + h];
        #pragma unroll
        for (int t = 0; t < 8; t++) acc[t] = fmaf(sE[(t0 + t) * 256 + h], wv, acc[t]);
    }
    int segoff = (g == 0) ? 0 : (g == 1) ? 2048 : (g == 2) ? 8192 : 18432;
    #pragma unroll
    for (int t = 0; t < 8; t++)
        g_U[segoff + (d * 32 + t0 + t) * 64 + cg] = acc[t];
}

// ---------------- K: conv via table lookups + BN partial stats (half output) ----------------
__global__ void k_conv() {
    extern __shared__ float sm[];
    float* sU   = sm;
    float* sRed = sm + 32768;
    __shared__ int sTok[256];
    int tx = threadIdx.x, ty = threadIdx.y;
    int tid = ty * 64 + tx;
    int n0 = blockIdx.x * 8;
    const float4* gU4 = (const float4*)g_U;
    float4* sU4 = (float4*)sU;
    for (int v = tid; v < 8192; v += 256) sU4[v] = gU4[v];
    if (tid < 256) sTok[tid] = g_tok[n0 * LSEQ + tid];
    __syncthreads();

    int g = tx >> 4, ks = 2 * g + 1, pad = g;
    int seg4 = (g == 0) ? 0 : (g == 1) ? 512 : (g == 2) ? 2048 : 4608;
    int cm = tx & 15;
    const float4* U4 = (const float4*)sU;
    float lsum[4] = {0, 0, 0, 0}, lsq[4] = {0, 0, 0, 0};

    for (int half = 0; half < 2; half++) {
        int nl = ty + 4 * half;
        int n = n0 + nl;
        const int* tk = sTok + nl * LSEQ;
        for (int l = 0; l < LSEQ; l++) {
            float4 acc = make_float4(0.f, 0.f, 0.f, 0.f);
            #pragma unroll
            for (int d = 0; d < 7; d++) {
                int lp = l + d - pad;
                if (d < ks && lp >= 0 && lp < LSEQ) {
                    float4 u = U4[seg4 + (d * 32 + tk[lp]) * 16 + cm];
                    acc.x += u.x; acc.y += u.y; acc.z += u.z; acc.w += u.w;
                }
            }
            __half2 p0 = __floats2half2_rn(acc.x, acc.y);
            __half2 p1 = __floats2half2_rn(acc.z, acc.w);
            __half2* dst = (__half2*)&g_conv16[(size_t)(n * LSEQ + l) * 256 + tx * 4];
            dst[0] = p0; dst[1] = p1;
            lsum[0] += acc.x; lsum[1] += acc.y; lsum[2] += acc.z; lsum[3] += acc.w;
            lsq[0] += acc.x * acc.x; lsq[1] += acc.y * acc.y;
            lsq[2] += acc.z * acc.z; lsq[3] += acc.w * acc.w;
        }
    }
    #pragma unroll
    for (int e = 0; e < 4; e++) {
        sRed[ty * 512 + 4 * tx + e]       = lsum[e];
        sRed[ty * 512 + 256 + 4 * tx + e] = lsq[e];
    }
    __syncthreads();
    if (tid < 256) {
        float s = sRed[tid] + sRed[512 + tid] + sRed[1024 + tid] + sRed[1536 + tid];
        float q = sRed[256 + tid] + sRed[768 + tid] + sRed[1280 + tid] + sRed[1792 + tid];
        g_bnPart[blockIdx.x * 512 + tid]       = s;
        g_bnPart[blockIdx.x * 512 + 256 + tid] = q;
    }
}

// ---------------- K: finalize BN ----------------
__global__ void k_bnfin(const float* __restrict__ bn_g, const float* __restrict__ bn_b) {
    int c = threadIdx.x;
    double s = 0.0, q = 0.0;
    for (int b = 0; b < 512; b++) {
        s += (double)g_bnPart[b * 512 + c];
        q += (double)g_bnPart[b * 512 + 256 + c];
    }
    double mean = s / (double)NL;
    double var  = q / (double)NL - mean * mean;
    float sc = (float)((double)bn_g[c] / sqrt(var + 1e-5));
    g_bnS[c] = sc;
    g_bnT[c] = bn_b[c] - sc * (float)mean;
}

// ---------------- K: fp16 mma GEMM  C[M x 768] = A[M x 256] @ W^T ----------------
// MODE 0: A = prelu(BN(g_conv16)) fused at staging, C = g_xproj
// MODE 1: A = g_h16,                               C = g_G
// CTA 128x128 tile, 8 warps (2M x 4N, warp 64x32), K chunk 32, cp.async double buffer.
template<int MODE>
__global__ void __launch_bounds__(256, 2) k_gemm16(const float* __restrict__ prelu_a) {
    __shared__ __half As[2][128][40];
    __shared__ __half Bs[2][128][40];
    int tid = threadIdx.x, lane = tid & 31, wid = tid >> 5;
    int wr = wid & 1, wc = wid >> 1;
    int m0 = blockIdx.x * 128, nc0 = blockIdx.y * 128;
    const __half* Ag = (MODE == 0) ? g_conv16 : g_h16;
    const __half* Bg = g_W16[MODE] + ((nc0 >> 8) * 65536 + (nc0 & 255) * 256);
    float* C = (MODE == 0) ? g_xproj : g_G;
    float ca = (MODE == 0) ? prelu_a[0] : 0.f;

    int arow = tid >> 1, acol = (tid & 1) * 16;
    const __half* Ap = Ag + (size_t)(m0 + arow) * 256 + acol;

    float acc[4][4][4];
    #pragma unroll
    for (int i = 0; i < 4; i++)
        #pragma unroll
        for (int j = 0; j < 4; j++)
            #pragma unroll
            for (int q = 0; q < 4; q++) acc[i][j][q] = 0.f;

    uint4 ar0, ar1;

    // prologue: stage chunk 0
    {
        const uint4* p = (const uint4*)(Ap);
        ar0 = p[0]; ar1 = p[1];
    }
    // STS A(0) and cp B(0) below via shared lambdas written inline:
    #define LDG_A(k0) { const uint4* p = (const uint4*)(Ap + (k0)); ar0 = p[0]; ar1 = p[1]; }
    #define STS_A(b, k0) {                                                                 \
        if (MODE == 0) {                                                                   \
            uint rawv[8]; *(uint4*)&rawv[0] = ar0; *(uint4*)&rawv[4] = ar1;                \
            uint outv[8];                                                                  \
            int cb = (k0) + acol;                                                          \
            _Pragma("unroll")                                                              \
            for (int u = 0; u < 8; u++) {                                                  \
                __half2 hv = *(__half2*)&rawv[u];                                          \
                float2 f = __half22float2(hv);                                             \
                int c = cb + 2 * u;                                                        \
                float x0 = fmaf(g_bnS[c],     f.x, g_bnT[c]);                              \
                x0 = x0 >= 0.f ? x0 : ca * x0;                                             \
                float x1 = fmaf(g_bnS[c + 1], f.y, g_bnT[c + 1]);                          \
                x1 = x1 >= 0.f ? x1 : ca * x1;                                             \
                __half2 o = __floats2half2_rn(x0, x1);                                     \
                outv[u] = *(uint*)&o;                                                      \
            }                                                                              \
            uint4* d = (uint4*)&As[b][arow][acol];                                         \
            d[0] = *(uint4*)&outv[0]; d[1] = *(uint4*)&outv[4];                            \
        } else {                                                                           \
            uint4* d = (uint4*)&As[b][arow][acol];                                         \
            d[0] = ar0; d[1] = ar1;                                                        \
        }                                                                                  \
    }
    #define CP_B(b, k0) {                                                                  \
        _Pragma("unroll")                                                                  \
        for (int it = 0; it < 2; it++) {                                                   \
            int idx = tid + it * 256;                                                      \
            int row = idx >> 2, kc = idx & 3;                                              \
            uint32_t dst = (uint32_t)__cvta_generic_to_shared(&Bs[b][row][kc * 8]);        \
            const __half* src = Bg + (size_t)row * 256 + (k0) + kc * 8;                    \
            asm volatile("cp.async.cg.shared.global [%0], [%1], 16;" :: "r"(dst), "l"(src)); \
        }                                                                                  \
        asm volatile("cp.async.commit_group;" ::: "memory");                               \
    }

    STS_A(0, 0);
    CP_B(0, 0);

    int buf = 0;
    #pragma unroll 1
    for (int c = 0; c < 8; c++) {
        if (c < 7) LDG_A((c + 1) * 32);
        asm volatile("cp.async.wait_group 0;" ::: "memory");
        __syncthreads();
        if (c < 7) CP_B(buf ^ 1, (c + 1) * 32);
        // ---- compute on buffer buf ----
        #pragma unroll
        for (int kk = 0; kk < 2; kk++) {
            uint a[4][4], bb[4][2];
            #pragma unroll
            for (int mi = 0; mi < 4; mi++) {
                uint32_t ad = (uint32_t)__cvta_generic_to_shared(
                    &As[buf][wr * 64 + mi * 16 + (lane & 15)][kk * 16 + (lane >> 4) * 8]);
                asm volatile("ldmatrix.sync.aligned.m8n8.x4.shared.b16 {%0,%1,%2,%3}, [%4];"
                    : "=r"(a[mi][0]), "=r"(a[mi][1]), "=r"(a[mi][2]), "=r"(a[mi][3]) : "r"(ad));
            }
            #pragma unroll
            for (int p = 0; p < 2; p++) {
                uint32_t bd = (uint32_t)__cvta_generic_to_shared(
                    &Bs[buf][wc * 32 + p * 16 + ((lane >> 4) << 3) + (lane & 7)]
                            [kk * 16 + ((lane >> 3) & 1) * 8]);
                uint r0, r1, r2, r3;
                asm volatile("ldmatrix.sync.aligned.m8n8.x4.shared.b16 {%0,%1,%2,%3}, [%4];"
                    : "=r"(r0), "=r"(r1), "=r"(r2), "=r"(r3) : "r"(bd));
                bb[2 * p][0] = r0; bb[2 * p][1] = r1;
                bb[2 * p + 1][0] = r2; bb[2 * p + 1][1] = r3;
            }
            #pragma unroll
            for (int mi = 0; mi < 4; mi++)
                #pragma unroll
                for (int ni = 0; ni < 4; ni++)
                    asm volatile("mma.sync.aligned.m16n8k16.row.col.f32.f16.f16.f32 "
                        "{%0,%1,%2,%3}, {%4,%5,%6,%7}, {%8,%9}, {%0,%1,%2,%3};"
                        : "+f"(acc[mi][ni][0]), "+f"(acc[mi][ni][1]),
                          "+f"(acc[mi][ni][2]), "+f"(acc[mi][ni][3])
                        : "r"(a[mi][0]), "r"(a[mi][1]), "r"(a[mi][2]), "r"(a[mi][3]),
                          "r"(bb[ni][0]), "r"(bb[ni][1]));
        }
        if (c < 7) STS_A(buf ^ 1, (c + 1) * 32);
        buf ^= 1;
    }

    // ---- epilogue ----
    #pragma unroll
    for (int mi = 0; mi < 4; mi++) {
        int m = m0 + wr * 64 + mi * 16 + (lane >> 2);
        #pragma unroll
        for (int ni = 0; ni < 4; ni++) {
            int n = nc0 + wc * 32 + ni * 8 + (lane & 3) * 2;
            *(float2*)&C[(size_t)m * 768 + n] =
                make_float2(acc[mi][ni][0], acc[mi][ni][1]);
            *(float2*)&C[(size_t)(m + 8) * 768 + n] =
                make_float2(acc[mi][ni][2], acc[mi][ni][3]);
        }
    }
    #undef LDG_A
    #undef STS_A
    #undef CP_B
}

// ---------------- K: GRU gate elementwise (per step) ----------------
__global__ void k_gate(int l, int hin, const float* __restrict__ bh,
                       const float* __restrict__ bx) {
    int i = blockIdx.x * 256 + threadIdx.x;
    int n = i >> 8, j = i & 255;
    float h = g_h[hin][i];
    const float* G = g_G + (size_t)n * 768 + j;
    float gr = G[0]   + __ldg(&bh[j]);
    float gz = G[256] + __ldg(&bh[256 + j]);
    float gn = G[512] + __ldg(&bh[512 + j]);
    size_t m = (size_t)n * 32 + l;
    const float* xp = g_xproj + m * 768 + j;
    float xr = xp[0]   + __ldg(&bx[j]);
    float xz = xp[256] + __ldg(&bx[256 + j]);
    float xn = xp[512] + __ldg(&bx[512 + j]);
    float r = __fdividef(1.f, 1.f + __expf(-(xr + gr)));
    float z = __fdividef(1.f, 1.f + __expf(-(xz + gz)));
    float arg = xn + r * gn;
    float e2 = __expf(2.f * arg);
    float th = 1.f - __fdividef(2.f, e2 + 1.f);
    float hn = th + z * (h - th);
    g_h[hin ^ 1][i] = hn;
    g_h16[i] = __float2half(hn);
}

// ---------------- K: final linear on c-path ----------------
__global__ void k_final(const float* __restrict__ Wl, const float* __restrict__ bl,
                        const float* __restrict__ a1p, const float* __restrict__ a2p,
                        float* __restrict__ out) {
    __shared__ float As[16 * 68];
    __shared__ float Bs[16 * 64];
    int m0 = blockIdx.x * 64;
    int j0 = blockIdx.y * 64;
    float a1 = a1p[0], a2 = a2p[0];
    const float* A = g_h[0];
    int tid = threadIdx.x;
    int tx = tid & 15, ty = tid >> 4;
    float acc[4][4];
    #pragma unroll
    for (int i = 0; i < 4; i++)
        #pragma unroll
        for (int j = 0; j < 4; j++) acc[i][j] = 0.f;

    for (int k0 = 0; k0 < H; k0 += 16) {
        int row = tid >> 2, segc = tid & 3;
        float4 a4 = *(const float4*)&A[(m0 + row) * H + k0 + 4 * segc];
        float av[4] = {a4.x, a4.y, a4.z, a4.w};
        #pragma unroll
        for (int e = 0; e < 4; e++) {
            float x = av[e];
            As[(4 * segc + e) * 68 + row] = x >= 0.f ? x : a1 * x;
        }
        int rowk = tid >> 4, jc = tid & 15;
        float4 b4 = *(const float4*)&Wl[(k0 + rowk) * H + j0 + 4 * jc];
        *(float4*)&Bs[rowk * 64 + 4 * jc] = b4;
        __syncthreads();
        #pragma unroll
        for (int k = 0; k < 16; k++) {
            float a[4], b[4];
            *(float4*)a = *(const float4*)&As[k * 68 + ty * 4];
            *(float4*)b = *(const float4*)&Bs[k * 64 + tx * 4];
            #pragma unroll
            for (int i = 0; i < 4; i++)
                #pragma unroll
                for (int j = 0; j < 4; j++)
                    acc[i][j] = fmaf(a[i], b[j], acc[i][j]);
        }
        __syncthreads();
    }
    #pragma unroll
    for (int i = 0; i < 4; i++) {
        int m = m0 + ty * 4 + i;
        #pragma unroll
        for (int j = 0; j < 4; j++) {
            int jj = j0 + tx * 4 + j;
            float v = acc[i][j] + bl[jj];
            v = v >= 0.f ? v : a2 * v;
            out[m * 512 + 256 + jj] = v;
        }
    }
}

// ---------------- K: obs output ----------------
__global__ void k_obsout(const float* __restrict__ obs_b, const float* __restrict__ obs_a_p,
                         float* __restrict__ out) {
    int m = blockIdx.x;
    int j = threadIdx.x;
    __shared__ int si[KOBS];
    if (j < KOBS) si[j] = g_idx[m * KOBS + j];
    __syncthreads();
    float acc = obs_b[j];
    #pragma unroll
    for (int k = 0; k < KOBS; k++)
        acc += g_M[(si[k] * KOBS + k) * H + j];
    float a = obs_a_p[0];
    out[m * 512 + j] = acc >= 0.f ? acc : a * acc;
}

// ---------------- host launch ----------------
extern "C" void kernel_launch(void* const* d_in, const int* in_sizes, int n_in,
                              void* d_out, int out_size) {
    const float* obs        = (const float*)d_in[0];
    const float* comm       = (const float*)d_in[1];
    const float* obs_emb    = (const float*)d_in[2];
    const float* obs_a_emb  = (const float*)d_in[3];
    const float* obs_W      = (const float*)d_in[4];
    const float* obs_b      = (const float*)d_in[5];
    const float* obs_a      = (const float*)d_in[6];
    const float* comm_emb   = (const float*)d_in[7];
    const float* comm_a_emb = (const float*)d_in[8];
    const float* cw1        = (const float*)d_in[9];
    const float* cw3        = (const float*)d_in[11];
    const float* cw5        = (const float*)d_in[13];
    const float* cw7        = (const float*)d_in[15];
    const float* bn_g       = (const float*)d_in[17];
    const float* bn_b       = (const float*)d_in[18];
    const float* cnn_a      = (const float*)d_in[19];
    const float* Wx         = (const float*)d_in[20];
    const float* bx         = (const float*)d_in[21];
    const float* Wh         = (const float*)d_in[22];
    const float* bh         = (const float*)d_in[23];
    const float* lin_a1     = (const float*)d_in[24];
    const float* lin_W      = (const float*)d_in[25];
    const float* lin_b      = (const float*)d_in[26];
    const float* lin_a2     = (const float*)d_in[27];
    float* out = (float*)d_out;

    cudaFuncSetAttribute(k_conv,  cudaFuncAttributeMaxDynamicSharedMemorySize, 139264);
    cudaFuncSetAttribute(k_commU, cudaFuncAttributeMaxDynamicSharedMemorySize, 98560);

    k_prep<<<dim3(8, 8, 6), dim3(32, 8)>>>(Wx, Wh);                  // 0
    k_extract<<<NES, 64>>>(obs, comm);                               // 1
    k_commU<<<dim3(4, 7), 256, 98560>>>(comm_emb, comm_a_emb, cw1, cw3, cw5, cw7); // 2
    k_conv<<<512, dim3(64, 4), 139264>>>();                          // 3
    k_bnfin<<<1, 256>>>(bn_g, bn_b);                                 // 4
    k_gemm16<0><<<dim3(1024, 6), 256>>>(cnn_a);                      // 5 (ncu target) xproj
    k_init<<<256, 256>>>();                                          // 6
    k_obsM<<<dim3(32, 8), 256>>>(obs_emb, obs_W, obs_a_emb);         // 7

    int hin = 0;
    for (int l = 0; l < LSEQ; l++) {
        k_gemm16<1><<<dim3(32, 6), 256>>>(nullptr);
        k_gate<<<NES, 256>>>(l, hin, bh, bx);
        hin ^= 1;
    }
    // after 32 gate steps, final state is in g_h[0]
    k_final<<<dim3(64, 4), 256>>>(lin_W, lin_b, lin_a1, lin_a2, out);
    k_obsout<<<NES, 256>>>(obs_b, obs_a, out);
}